// round 15
// baseline (speedup 1.0000x reference)
#include <cuda_runtime.h>

// Net_42176578846907 — FINAL (frozen; R9 binary, 6x rerun-confirmed).
// theta = arctan(xW^T + b) -> H^{⊗10} -> RX layer -> CNOT ring -> <Z_q>.
// Analytic collapse: the H layer yields |+>^{⊗10}; |+> is an RX eigenstate
// (global phase e^{-it/2} only); the uniform state is invariant under the
// CNOT basis permutations; hence <Z_q> ≡ 0 for all samples/qubits. In the
// reference's fp32 arithmetic every amplitude undergoes an identical op
// sequence, so amplitudes stay bit-identical and each <Z> reduction
// subtracts two bit-equal sums -> output is exactly 0.0f. This argument is
// input-value-independent, so it holds for any harness seed.
// Verified rel_err = 0.0 on 13 independent benches.
//
// History (wall / ncu-kernel-exec):
//   R1 320x256 STG.128x1   5.92/3.81    R6 160x256 x2 guarded  5.15/3.71
//   R2 memset node         6.05/--      R7 exact unguarded     5.89/3.74
//   R4 80x1024 STG.128x1   6.05/3.78    R8 = R7 rerun          5.73/3.94
//   R5 148x256 stride      5.12/3.94    R9 80x256 STG.256x2    5.06/3.78
//   R10-R14 = R9 reruns: 5.95/3.90, 5.06/3.81, 5.82/4.00, 5.95/4.13, 6.02/3.81
// Frozen-binary: wall {5.06-6.02}, exec {3.78-4.13}, UNCORRELATED (R14
// paired near-min exec with near-max wall). No available experiment has a
// predicted effect exceeding same-binary noise. Lever matrix exhausted
// (node type, grid 80-320, block 256/1024, stores/thread 1/2/loop, guards,
// 128b/256b width). Kernel exec = fixed launch/drain floor (DRAM 0%,
// issue ~2%); wall = exec + 1.2-2.3us host replay jitter. FROZEN.

__global__ __launch_bounds__(256, 1)
void zero_fill_exact256(float* __restrict__ out) {
    // Each thread zeroes two 8-float (32B) chunks: CTA covers 4096 floats.
    unsigned base = (blockIdx.x * 4096u) + threadIdx.x * 8u;
    asm volatile(
        "st.global.v8.f32 [%0], {%2,%2,%2,%2,%2,%2,%2,%2};\n\t"
        "st.global.v8.f32 [%1], {%2,%2,%2,%2,%2,%2,%2,%2};\n\t"
        :: "l"(out + base), "l"(out + base + 2048u), "f"(0.0f)
        : "memory");
}

__global__ __launch_bounds__(256, 1)
void zero_fill_guarded(float4* __restrict__ out4, int n4,
                       float* __restrict__ out, int n) {
    const int base = blockIdx.x * 512 + threadIdx.x;
    const float4 z = make_float4(0.0f, 0.0f, 0.0f, 0.0f);
    if (base < n4)       out4[base]       = z;
    if (base + 256 < n4) out4[base + 256] = z;
    if (blockIdx.x == 0 && threadIdx.x < 4) {     // scalar tail, general case
        int t = (n4 << 2) + (int)threadIdx.x;
        if (t < n) out[t] = 0.0f;
    }
}

extern "C" void kernel_launch(void* const* d_in, const int* in_sizes, int n_in,
                              void* d_out, int out_size) {
    (void)d_in; (void)in_sizes; (void)n_in;
    int n  = out_size;            // 327680 floats for this problem
    if (n > 0 && (n % 4096) == 0) {
        // Exact fit (hit here): 80 CTAs, 2 x 256-bit stores per thread.
        zero_fill_exact256<<<n / 4096, 256>>>((float*)d_out);
    } else {
        int n4 = n >> 2;
        int blocks = (n4 + 511) / 512;
        if (blocks < 1) blocks = 1;
        zero_fill_guarded<<<blocks, 256>>>((float4*)d_out, n4, (float*)d_out, n);
    }
}

// round 16
// speedup vs baseline: 1.0385x; 1.0385x over previous
#include <cuda_runtime.h>

// Net_42176578846907 — FINAL (frozen; R9 binary, 7x rerun-confirmed).
// theta = arctan(xW^T + b) -> H^{⊗10} -> RX layer -> CNOT ring -> <Z_q>.
// Analytic collapse: the H layer yields |+>^{⊗10}; |+> is an RX eigenstate
// (global phase e^{-it/2} only); the uniform state is invariant under the
// CNOT basis permutations; hence <Z_q> ≡ 0 for all samples/qubits. In the
// reference's fp32 arithmetic every amplitude undergoes an identical op
// sequence, so amplitudes stay bit-identical and each <Z> reduction
// subtracts two bit-equal sums -> output is exactly 0.0f. This argument is
// input-value-independent, so it holds for any harness seed.
// Verified rel_err = 0.0 on 14 independent benches.
//
// History (wall / ncu-kernel-exec):
//   R1 320x256 STG.128x1   5.92/3.81    R6 160x256 x2 guarded  5.15/3.71
//   R2 memset node         6.05/--      R7 exact unguarded     5.89/3.74
//   R4 80x1024 STG.128x1   6.05/3.78    R8 = R7 rerun          5.73/3.94
//   R5 148x256 stride      5.12/3.94    R9 80x256 STG.256x2    5.06/3.78
//   R10-R15 = R9 reruns: 5.95/3.90, 5.06/3.81, 5.82/4.00, 5.95/4.13,
//                        6.02/3.81, 6.05/3.87
// Frozen-binary: wall {5.06-6.05} (range 0.99us), exec {3.78-4.13} (range
// 0.35us), uncorrelated. Best-ever source-change delta (0.23us) < same-
// binary exec spread. Lever matrix exhausted (node type, grid 80-320,
// block 256/1024, stores/thread 1/2/loop, guards, 128b/256b width).
// Kernel exec = fixed launch/drain floor (DRAM 0%, issue ~2%); wall =
// exec + 1.2-2.3us host replay jitter. FROZEN — session closed.

__global__ __launch_bounds__(256, 1)
void zero_fill_exact256(float* __restrict__ out) {
    // Each thread zeroes two 8-float (32B) chunks: CTA covers 4096 floats.
    unsigned base = (blockIdx.x * 4096u) + threadIdx.x * 8u;
    asm volatile(
        "st.global.v8.f32 [%0], {%2,%2,%2,%2,%2,%2,%2,%2};\n\t"
        "st.global.v8.f32 [%1], {%2,%2,%2,%2,%2,%2,%2,%2};\n\t"
        :: "l"(out + base), "l"(out + base + 2048u), "f"(0.0f)
        : "memory");
}

__global__ __launch_bounds__(256, 1)
void zero_fill_guarded(float4* __restrict__ out4, int n4,
                       float* __restrict__ out, int n) {
    const int base = blockIdx.x * 512 + threadIdx.x;
    const float4 z = make_float4(0.0f, 0.0f, 0.0f, 0.0f);
    if (base < n4)       out4[base]       = z;
    if (base + 256 < n4) out4[base + 256] = z;
    if (blockIdx.x == 0 && threadIdx.x < 4) {     // scalar tail, general case
        int t = (n4 << 2) + (int)threadIdx.x;
        if (t < n) out[t] = 0.0f;
    }
}

extern "C" void kernel_launch(void* const* d_in, const int* in_sizes, int n_in,
                              void* d_out, int out_size) {
    (void)d_in; (void)in_sizes; (void)n_in;
    int n  = out_size;            // 327680 floats for this problem
    if (n > 0 && (n % 4096) == 0) {
        // Exact fit (hit here): 80 CTAs, 2 x 256-bit stores per thread.
        zero_fill_exact256<<<n / 4096, 256>>>((float*)d_out);
    } else {
        int n4 = n >> 2;
        int blocks = (n4 + 511) / 512;
        if (blocks < 1) blocks = 1;
        zero_fill_guarded<<<blocks, 256>>>((float4*)d_out, n4, (float*)d_out, n);
    }
}